// round 1
// baseline (speedup 1.0000x reference)
#include <cuda_runtime.h>
#include <math.h>

// Problem constants (fixed by setup_inputs)
#define I_N 1024
#define O_N 36
#define C_N 1024
#define W_N 60
#define D_N 64
#define MARGIN 0.2f

// Tiling
#define IMG_PER_BLK 4
#define CAP_PER_BLK 8
#define ROWS 144          // IMG_PER_BLK * O_N
#define A_STRIDE 145      // odd stride -> conflict-free column access
#define B_STRIDE 66       // even stride -> float2-aligned word pairs
#define THREADS 128

// Dynamic smem layout (floats)
#define SM_A 0            // 64 x 145 = 9280
#define SM_B 9280         // 64 x 66  = 4224
#define SM_RED 13504      // 8 x 144  = 1152
#define SM_RMAX 14656     // 144
#define SM_INV 14800      // 4
#define SM_FLOATS 14804
#define SMEM_BYTES (SM_FLOATS * 4)

__device__ float g_scores[(size_t)I_N * C_N];
__device__ float g_diag[I_N];
__device__ float g_partial[I_N];

typedef unsigned long long ull;

__device__ __forceinline__ ull pk2(float x) {
    ull r; asm("mov.b64 %0, {%1, %1};" : "=l"(r) : "f"(x)); return r;
}
__device__ __forceinline__ void fma2(ull &d, ull a, ull b) {
    asm("fma.rn.f32x2 %0, %1, %2, %0;" : "+l"(d) : "l"(a), "l"(b));
}
__device__ __forceinline__ float2 up2(ull x) {
    float2 f; asm("mov.b64 {%0, %1}, %2;" : "=f"(f.x), "=f"(f.y) : "l"(x)); return f;
}

extern "C" __global__ void __launch_bounds__(THREADS)
scores_kernel(const float* __restrict__ im, const float* __restrict__ s,
              const int* __restrict__ im_l, const int* __restrict__ s_l)
{
    extern __shared__ float sm[];
    float* A    = sm + SM_A;     // transposed im tile: A[d][row], row in [0,144)
    float* B    = sm + SM_B;     // transposed s tile:  B[d][w],   w in [0,64) (60..63 pad)
    float* red  = sm + SM_RED;   // per-tx row maxes
    float* rmax = sm + SM_RMAX;  // final row maxes
    float* inv  = sm + SM_INV;   // 1/(obj+eps) per image

    const int tid  = threadIdx.x;
    const int tx   = tid >> 4;        // 0..7  -> column group (8 words)
    const int ty   = tid & 15;        // 0..15 -> row group (9 rows)
    const int warp = tid >> 5;        // warp w covers word columns [16w, 16w+16)
    const int i0   = blockIdx.y * IMG_PER_BLK;
    const int c0   = blockIdx.x * CAP_PER_BLK;
    const int r0   = ty * 9;
    const int cbase = tx * 8;

    if (tid < IMG_PER_BLK)
        inv[tid] = 1.0f / ((float)im_l[i0 + tid] + 1e-6f);

    // Load A (4 images x 36 x 64) transposed into smem, float4 global reads.
    {
        const float4* imA = (const float4*)(im + (size_t)i0 * O_N * D_N);
        #pragma unroll
        for (int t = 0; t < 18; ++t) {
            int e = tid + THREADS * t;      // float4 index, 0..2303
            float4 v = imA[e];
            int row = e >> 4;               // e*4/64
            int d   = (e & 15) << 2;
            A[(d + 0) * A_STRIDE + row] = v.x;
            A[(d + 1) * A_STRIDE + row] = v.y;
            A[(d + 2) * A_STRIDE + row] = v.z;
            A[(d + 3) * A_STRIDE + row] = v.w;
        }
    }
    // Pad word columns 60..63 once (values irrelevant; masked in reduction).
    for (int idx = tid; idx < 64 * 4; idx += THREADS) {
        int d = idx >> 2; int w = 60 + (idx & 3);
        B[d * B_STRIDE + w] = 0.0f;
    }

    for (int cap = 0; cap < CAP_PER_BLK; ++cap) {
        const int c = c0 + cap;
        const int clen = s_l[c];

        // Load B (60 x 64) transposed into smem.
        {
            const float4* sC = (const float4*)(s + (size_t)c * W_N * D_N);
            #pragma unroll
            for (int t = 0; t < 8; ++t) {
                int e = tid + THREADS * t;  // 0..959 valid
                if (e < 960) {
                    float4 v = sC[e];
                    int w = e >> 4;
                    int d = (e & 15) << 2;
                    B[(d + 0) * B_STRIDE + w] = v.x;
                    B[(d + 1) * B_STRIDE + w] = v.y;
                    B[(d + 2) * B_STRIDE + w] = v.z;
                    B[(d + 3) * B_STRIDE + w] = v.w;
                }
            }
        }
        __syncthreads();   // S1: B (and A on first iter) ready

        ull acc[9][4];
        #pragma unroll
        for (int k = 0; k < 9; ++k)
            #pragma unroll
            for (int j = 0; j < 4; ++j) acc[k][j] = 0ULL;

        // Warp-level word skip: warp covers cols [16*warp, 16*warp+16);
        // if all of them >= clen the dots are masked away -> skip compute.
        if (warp * 16 < clen) {
            #pragma unroll 4
            for (int d = 0; d < 64; ++d) {
                const ull* b = (const ull*)(B + d * B_STRIDE + cbase);
                ull b0 = b[0], b1 = b[1], b2 = b[2], b3 = b[3];
                const float* a = A + d * A_STRIDE + r0;
                #pragma unroll
                for (int k = 0; k < 9; ++k) {
                    ull aa = pk2(a[k]);
                    fma2(acc[k][0], aa, b0);
                    fma2(acc[k][1], aa, b1);
                    fma2(acc[k][2], aa, b2);
                    fma2(acc[k][3], aa, b3);
                }
            }
        }

        // Per-thread masked max over its 8 word columns.
        #pragma unroll
        for (int k = 0; k < 9; ++k) {
            float m = -1e30f;
            #pragma unroll
            for (int j = 0; j < 4; ++j) {
                float2 v = up2(acc[k][j]);
                int col = cbase + 2 * j;
                if (col < clen)     m = fmaxf(m, v.x);
                if (col + 1 < clen) m = fmaxf(m, v.y);
            }
            red[tx * ROWS + r0 + k] = m;
        }
        __syncthreads();   // S2: red ready

        // Cross-tx max -> full row max.
        for (int rr = tid; rr < ROWS; rr += THREADS) {
            float m = red[rr];
            #pragma unroll
            for (int t = 1; t < 8; ++t) m = fmaxf(m, red[t * ROWS + rr]);
            rmax[rr] = m;
        }
        __syncthreads();   // S3: rmax ready

        // Per-image sum over all 36 rows, scale, store (no atomics).
        if (tid < IMG_PER_BLK) {
            float ssum = 0.0f;
            #pragma unroll
            for (int o = 0; o < O_N; ++o) ssum += rmax[tid * O_N + o];
            g_scores[(size_t)(i0 + tid) * C_N + c] = ssum * inv[tid];
        }
        __syncthreads();   // S4: protect smem buffers before next iteration
    }
}

extern "C" __global__ void diag_kernel()
{
    int i = blockIdx.x * blockDim.x + threadIdx.x;
    if (i < I_N) g_diag[i] = g_scores[(size_t)i * C_N + i];
}

extern "C" __global__ void row_kernel()
{
    const int b = blockIdx.x;
    const int tid = threadIdx.x;
    const float di = g_diag[b];
    float local = 0.0f;
    for (int c = tid; c < C_N; c += blockDim.x) {
        if (c == b) continue;
        float sc = g_scores[(size_t)b * C_N + c];
        local += fmaxf(0.0f, MARGIN + sc - di)
               + fmaxf(0.0f, MARGIN + sc - g_diag[c]);
    }
    __shared__ float buf[128];
    buf[tid] = local;
    __syncthreads();
    for (int s = 64; s > 0; s >>= 1) {
        if (tid < s) buf[tid] += buf[tid + s];
        __syncthreads();
    }
    if (tid == 0) g_partial[b] = buf[0];
}

extern "C" __global__ void final_kernel(float* out)
{
    const int tid = threadIdx.x;
    float local = 0.0f;
    for (int i = tid; i < I_N; i += 256) local += g_partial[i];
    __shared__ float buf[256];
    buf[tid] = local;
    __syncthreads();
    for (int s = 128; s > 0; s >>= 1) {
        if (tid < s) buf[tid] += buf[tid + s];
        __syncthreads();
    }
    if (tid == 0) out[0] = buf[0] * (1.0f / ((float)I_N * (float)C_N));
}

extern "C" void kernel_launch(void* const* d_in, const int* in_sizes, int n_in,
                              void* d_out, int out_size)
{
    const float* im   = (const float*)d_in[0];
    const float* s    = (const float*)d_in[1];
    const int*   im_l = (const int*)d_in[2];
    const int*   s_l  = (const int*)d_in[3];

    // Idempotent, non-stream API; safe pre-capture and during capture.
    cudaFuncSetAttribute(scores_kernel,
                         cudaFuncAttributeMaxDynamicSharedMemorySize, SMEM_BYTES);

    dim3 grid(C_N / CAP_PER_BLK, I_N / IMG_PER_BLK);   // (128, 256)
    scores_kernel<<<grid, THREADS, SMEM_BYTES>>>(im, s, im_l, s_l);
    diag_kernel<<<I_N / 256, 256>>>();
    row_kernel<<<I_N, 128>>>();
    final_kernel<<<1, 256>>>((float*)d_out);
}

// round 3
// speedup vs baseline: 2.2912x; 2.2912x over previous
#include <cuda_runtime.h>
#include <cuda_bf16.h>
#include <stdint.h>

// ---------------- problem constants ----------------
#define I_N 1024
#define O_N 36
#define C_N 1024
#define W_N 60
#define D_N 64
#define MARGIN 0.2f

#define IMG_PER_CTA 7
#define NCTA 147            // ceil(1024/7)
#define THREADS 256         // 8 warps; warp w owns m16-tiles w and w+8 (256 rows)

// ---------------- smem layout (bytes from 1024-aligned base) ----------------
#define OFF_AH   0          // 256 rows x 128B (bf16 hi)      = 32768
#define OFF_AL   32768      // 256 rows x 128B (bf16 lo)      = 32768
#define OFF_B    65536      // 2 bufs x (Bh 8KB + Bl 8KB)     = 32768
#define OFF_RMAX 98304      // 256 floats                     = 1024
#define OFF_INV  99328      // 7 floats
#define SMEM_BYTES (99360 + 1024)

// ---------------- device globals ----------------
__device__ __nv_bfloat16 gAh[(size_t)I_N * O_N * D_N];
__device__ __nv_bfloat16 gAl[(size_t)I_N * O_N * D_N];
__device__ __nv_bfloat16 gBh[(size_t)C_N * 64 * D_N];   // words padded to 64
__device__ __nv_bfloat16 gBl[(size_t)C_N * 64 * D_N];
__device__ float g_scores[(size_t)I_N * C_N];
__device__ float g_diag[I_N];
__device__ float g_partial[I_N];

// ---------------- helpers ----------------
__device__ __forceinline__ uint32_t smem_u32(const void* p) {
    uint32_t a;
    asm("{ .reg .u64 t; cvta.to.shared.u64 t, %1; cvt.u32.u64 %0, t; }" : "=r"(a) : "l"(p));
    return a;
}
#define SW128(off) ((off) ^ (((off) >> 3) & 0x70))

__device__ __forceinline__ void ldsm4(uint32_t* r, uint32_t addr) {
    asm volatile("ldmatrix.sync.aligned.m8n8.x4.shared.b16 {%0,%1,%2,%3}, [%4];"
                 : "=r"(r[0]), "=r"(r[1]), "=r"(r[2]), "=r"(r[3]) : "r"(addr));
}
__device__ __forceinline__ void ldsm2(uint32_t* r, uint32_t addr) {
    asm volatile("ldmatrix.sync.aligned.m8n8.x2.shared.b16 {%0,%1}, [%2];"
                 : "=r"(r[0]), "=r"(r[1]) : "r"(addr));
}
__device__ __forceinline__ void mma16816(float* d, const uint32_t* a, const uint32_t* b) {
    asm volatile(
        "mma.sync.aligned.m16n8k16.row.col.f32.bf16.bf16.f32 "
        "{%0,%1,%2,%3}, {%4,%5,%6,%7}, {%8,%9}, {%0,%1,%2,%3};"
        : "+f"(d[0]), "+f"(d[1]), "+f"(d[2]), "+f"(d[3])
        : "r"(a[0]), "r"(a[1]), "r"(a[2]), "r"(a[3]), "r"(b[0]), "r"(b[1]));
}
#define CP16(dst, src) \
    asm volatile("cp.async.cg.shared.global [%0], [%1], 16;" :: "r"(dst), "l"(src))
#define CP_COMMIT()  asm volatile("cp.async.commit_group;" ::: "memory")
#define CP_WAIT(n)   asm volatile("cp.async.wait_group %0;" :: "n"(n) : "memory")

// ---------------- precompute: fp32 -> bf16 hi/lo splits ----------------
extern "C" __global__ void convA_kernel(const float* __restrict__ im)
{
    size_t idx = (size_t)blockIdx.x * blockDim.x + threadIdx.x;
    if (idx >= (size_t)I_N * O_N * D_N) return;
    float a = im[idx];
    __nv_bfloat16 hi = __float2bfloat16(a);
    __nv_bfloat16 lo = __float2bfloat16(a - __bfloat162float(hi));
    gAh[idx] = hi; gAl[idx] = lo;
}

extern "C" __global__ void convB_kernel(const float* __restrict__ s)
{
    size_t idx = (size_t)blockIdx.x * blockDim.x + threadIdx.x;
    if (idx >= (size_t)C_N * 64 * D_N) return;
    int d = idx & 63;
    int w = ((int)idx >> 6) & 63;
    int c = (int)(idx >> 12);
    float v = (w < W_N) ? s[((size_t)c * W_N + w) * D_N + d] : 0.0f;
    __nv_bfloat16 hi = __float2bfloat16(v);
    __nv_bfloat16 lo = __float2bfloat16(v - __bfloat162float(hi));
    gBh[idx] = hi; gBl[idx] = lo;
}

// ---------------- main xattn-scores kernel (mma.sync bf16) ----------------
extern "C" __global__ void __launch_bounds__(THREADS, 1)
xattn_kernel(const int* __restrict__ im_l, const int* __restrict__ s_l)
{
    extern __shared__ char smraw[];
    const uint32_t raw_u = smem_u32(smraw);
    const uint32_t abase = (raw_u + 1023u) & ~1023u;
    char* base = smraw + (abase - raw_u);

    const int tid  = threadIdx.x;
    const int wid  = tid >> 5;          // 0..7
    const int lane = tid & 31;
    const int img0 = blockIdx.x * IMG_PER_CTA;
    const int n_img = (I_N - img0 < IMG_PER_CTA) ? (I_N - img0) : IMG_PER_CTA;

    float* rmax = (float*)(base + OFF_RMAX);
    float* inv  = (float*)(base + OFF_INV);
    if (tid < n_img)
        inv[tid] = 1.0f / ((float)im_l[img0 + tid] + 1e-6f);

    // ---- stage A (hi/lo) into swizzled smem; zero-pad rows >= n_img*36 ----
    {
        const int vchunks = n_img * O_N * 8;            // 16B chunks of valid rows
        const uint4* gh = (const uint4*)(gAh + (size_t)img0 * O_N * D_N);
        const uint4* gl = (const uint4*)(gAl + (size_t)img0 * O_N * D_N);
        const uint4 z = make_uint4(0, 0, 0, 0);
        #pragma unroll
        for (int t = tid; t < 2048; t += THREADS) {
            uint32_t off = SW128((uint32_t)(t * 16));
            *(uint4*)(base + OFF_AH + off) = (t < vchunks) ? gh[t] : z;
            *(uint4*)(base + OFF_AL + off) = (t < vchunks) ? gl[t] : z;
        }
    }

    // ---- prefetch B(0) ----
    {
        const char* sh = (const char*)(gBh);
        const char* sl = (const char*)(gBl);
        uint32_t dst = abase + OFF_B;
        #pragma unroll
        for (int t = tid; t < 512; t += THREADS) {
            uint32_t off = SW128((uint32_t)(t * 16));
            CP16(dst + off,        sh + t * 16);
            CP16(dst + 8192 + off, sl + t * 16);
        }
    }
    CP_COMMIT();
    __syncthreads();

    // per-thread ldmatrix addressing invariants
    const uint32_t xr    = (uint32_t)((lane & 7) << 4);       // swizzle XOR term
    const uint32_t aColB = (uint32_t)((lane >> 4) << 4);      // A col base (x4)
    const uint32_t bColB = (uint32_t)(((lane >> 3) & 1) << 4);// B col base (x2)
    const uint32_t aRow0 = (uint32_t)(wid * 16 + (lane & 15));        // mtile wid
    const uint32_t aRow1 = aRow0 + 128;                                // mtile wid+8
    const uint32_t bRowOff = (uint32_t)((lane & 7) * 128);

    for (int c = 0; c < C_N; ++c) {
        // prefetch B(c+1)
        if (c + 1 < C_N) {
            const char* sh = (const char*)(gBh + (size_t)(c + 1) * 4096);
            const char* sl = (const char*)(gBl + (size_t)(c + 1) * 4096);
            uint32_t dst = abase + OFF_B + (uint32_t)((c + 1) & 1) * 16384;
            #pragma unroll
            for (int t = tid; t < 512; t += THREADS) {
                uint32_t off = SW128((uint32_t)(t * 16));
                CP16(dst + off,        sh + t * 16);
                CP16(dst + 8192 + off, sl + t * 16);
            }
            CP_COMMIT();
            CP_WAIT(1);
        } else {
            CP_WAIT(0);
        }
        __syncthreads();   // B(c) ready; prev-iter rmax/score reads done

        const int clen = __ldg(&s_l[c]);
        const int nlim = (clen + 7) >> 3;
        const uint32_t bh_base = abase + OFF_B + (uint32_t)(c & 1) * 16384;
        const uint32_t bl_base = bh_base + 8192;

        float acc[2][8][4];
        #pragma unroll
        for (int m = 0; m < 2; ++m)
            #pragma unroll
            for (int n = 0; n < 8; ++n)
                #pragma unroll
                for (int j = 0; j < 4; ++j) acc[m][n][j] = 0.0f;

        #pragma unroll
        for (int k = 0; k < 4; ++k) {
            const uint32_t colA = (aColB + (uint32_t)(k * 32)) ^ xr;
            const uint32_t colB = (bColB + (uint32_t)(k * 32)) ^ xr;
            uint32_t ah0[4], ah1[4], al0[4], al1[4];
            ldsm4(ah0, abase + OFF_AH + aRow0 * 128 + colA);
            ldsm4(ah1, abase + OFF_AH + aRow1 * 128 + colA);
            ldsm4(al0, abase + OFF_AL + aRow0 * 128 + colA);
            ldsm4(al1, abase + OFF_AL + aRow1 * 128 + colA);
            #pragma unroll
            for (int n = 0; n < 8; ++n) {
                if (n < nlim) {
                    uint32_t bh[2], bl[2];
                    const uint32_t bro = (uint32_t)(n * 1024) + bRowOff + colB;
                    ldsm2(bh, bh_base + bro);
                    mma16816(acc[0][n], ah0, bh);
                    mma16816(acc[1][n], ah1, bh);
                    mma16816(acc[0][n], al0, bh);
                    mma16816(acc[1][n], al1, bh);
                    ldsm2(bl, bl_base + bro);
                    mma16816(acc[0][n], ah0, bl);
                    mma16816(acc[1][n], ah1, bl);
                }
            }
        }

        // ---- epilogue: masked word-max per row ----
        #pragma unroll
        for (int m = 0; m < 2; ++m) {
            float mlo = -1e30f, mhi = -1e30f;
            #pragma unroll
            for (int n = 0; n < 8; ++n) {
                if (n < nlim) {
                    const int col = n * 8 + (lane & 3) * 2;
                    if (col < clen)     { mlo = fmaxf(mlo, acc[m][n][0]);
                                          mhi = fmaxf(mhi, acc[m][n][2]); }
                    if (col + 1 < clen) { mlo = fmaxf(mlo, acc[m][n][1]);
                                          mhi = fmaxf(mhi, acc[m][n][3]); }
                }
            }
            // reduce across the 4 lanes of the quad (same rows)
            mlo = fmaxf(mlo, __shfl_xor_sync(0xFFFFFFFFu, mlo, 1));
            mlo = fmaxf(mlo, __shfl_xor_sync(0xFFFFFFFFu, mlo, 2));
            mhi = fmaxf(mhi, __shfl_xor_sync(0xFFFFFFFFu, mhi, 1));
            mhi = fmaxf(mhi, __shfl_xor_sync(0xFFFFFFFFu, mhi, 2));
            if ((lane & 3) == 0) {
                const int rowg = (m ? wid + 8 : wid) * 16 + (lane >> 2);
                rmax[rowg]     = mlo;
                rmax[rowg + 8] = mhi;
            }
        }
        __syncthreads();   // rmax ready

        if (tid < n_img) {
            float ssum = 0.0f;
            #pragma unroll
            for (int o = 0; o < O_N; ++o) ssum += rmax[tid * O_N + o];
            g_scores[(size_t)(img0 + tid) * C_N + c] = ssum * inv[tid];
        }
        // WAR on rmax covered by the syncthreads at the top of next iteration
    }
}

// ---------------- loss epilogue (validated in R1) ----------------
extern "C" __global__ void diag_kernel()
{
    int i = blockIdx.x * blockDim.x + threadIdx.x;
    if (i < I_N) g_diag[i] = g_scores[(size_t)i * C_N + i];
}

extern "C" __global__ void row_kernel()
{
    const int b = blockIdx.x;
    const int tid = threadIdx.x;
    const float di = g_diag[b];
    float local = 0.0f;
    for (int c = tid; c < C_N; c += blockDim.x) {
        if (c == b) continue;
        float sc = g_scores[(size_t)b * C_N + c];
        local += fmaxf(0.0f, MARGIN + sc - di)
               + fmaxf(0.0f, MARGIN + sc - g_diag[c]);
    }
    __shared__ float buf[128];
    buf[tid] = local;
    __syncthreads();
    for (int s = 64; s > 0; s >>= 1) {
        if (tid < s) buf[tid] += buf[tid + s];
        __syncthreads();
    }
    if (tid == 0) g_partial[b] = buf[0];
}

extern "C" __global__ void final_kernel(float* out)
{
    const int tid = threadIdx.x;
    float local = 0.0f;
    for (int i = tid; i < I_N; i += 256) local += g_partial[i];
    __shared__ float buf[256];
    buf[tid] = local;
    __syncthreads();
    for (int s = 128; s > 0; s >>= 1) {
        if (tid < s) buf[tid] += buf[tid + s];
        __syncthreads();
    }
    if (tid == 0) out[0] = buf[0] * (1.0f / ((float)I_N * (float)C_N));
}

// ---------------- launch ----------------
extern "C" void kernel_launch(void* const* d_in, const int* in_sizes, int n_in,
                              void* d_out, int out_size)
{
    const float* im   = (const float*)d_in[0];
    const float* s    = (const float*)d_in[1];
    const int*   im_l = (const int*)d_in[2];
    const int*   s_l  = (const int*)d_in[3];

    cudaFuncSetAttribute(xattn_kernel,
                         cudaFuncAttributeMaxDynamicSharedMemorySize, SMEM_BYTES);

    convA_kernel<<<(I_N * O_N * D_N + 255) / 256, 256>>>(im);
    convB_kernel<<<(C_N * 64 * D_N + 255) / 256, 256>>>(s);
    xattn_kernel<<<NCTA, THREADS, SMEM_BYTES>>>(im_l, s_l);
    diag_kernel<<<I_N / 256, 256>>>();
    row_kernel<<<I_N, 128>>>();
    final_kernel<<<1, 256>>>((float*)d_out);
}

// round 4
// speedup vs baseline: 4.1104x; 1.7940x over previous
#include <cuda_runtime.h>
#include <cuda_bf16.h>
#include <stdint.h>

// ---------------- problem constants ----------------
#define I_N 1024
#define O_N 36
#define C_N 1024
#define W_N 60
#define D_N 64
#define MARGIN 0.2f

#define IMG_PER_CTA 7
#define NCTA 147            // ceil(1024/7)
#define THREADS 256         // 8 warps; warp w owns m16-tiles w and w+8 (256 rows)

// ---------------- smem layout (bytes from 1024-aligned base) ----------------
#define OFF_AH   0          // 256 rows x 128B (bf16 hi)      = 32768
#define OFF_AL   32768      // 256 rows x 128B (bf16 lo)      = 32768
#define OFF_B    65536      // 2 bufs x 8KB (Bh only)         = 16384
#define OFF_RMAX 81920      // 256 floats                     = 1024
#define OFF_INV  82944      // 7 floats
#define SMEM_BYTES (82976 + 1024)

// ---------------- device globals ----------------
__device__ __nv_bfloat16 gAh[(size_t)I_N * O_N * D_N];
__device__ __nv_bfloat16 gAl[(size_t)I_N * O_N * D_N];
__device__ __nv_bfloat16 gBh[(size_t)C_N * 64 * D_N];   // words padded to 64 w/ duplicate of last valid word
__device__ float g_scores[(size_t)I_N * C_N];
__device__ float g_diag[I_N];
__device__ float g_partial[I_N];

// ---------------- helpers ----------------
__device__ __forceinline__ uint32_t smem_u32(const void* p) {
    uint32_t a;
    asm("{ .reg .u64 t; cvta.to.shared.u64 t, %1; cvt.u32.u64 %0, t; }" : "=r"(a) : "l"(p));
    return a;
}
#define SW128(off) ((off) ^ (((off) >> 3) & 0x70))

__device__ __forceinline__ void ldsm4(uint32_t* r, uint32_t addr) {
    asm volatile("ldmatrix.sync.aligned.m8n8.x4.shared.b16 {%0,%1,%2,%3}, [%4];"
                 : "=r"(r[0]), "=r"(r[1]), "=r"(r[2]), "=r"(r[3]) : "r"(addr));
}
__device__ __forceinline__ void ldsm2(uint32_t* r, uint32_t addr) {
    asm volatile("ldmatrix.sync.aligned.m8n8.x2.shared.b16 {%0,%1}, [%2];"
                 : "=r"(r[0]), "=r"(r[1]) : "r"(addr));
}
__device__ __forceinline__ void mma16816(float* d, const uint32_t* a, const uint32_t* b) {
    asm volatile(
        "mma.sync.aligned.m16n8k16.row.col.f32.bf16.bf16.f32 "
        "{%0,%1,%2,%3}, {%4,%5,%6,%7}, {%8,%9}, {%0,%1,%2,%3};"
        : "+f"(d[0]), "+f"(d[1]), "+f"(d[2]), "+f"(d[3])
        : "r"(a[0]), "r"(a[1]), "r"(a[2]), "r"(a[3]), "r"(b[0]), "r"(b[1]));
}
#define CP16(dst, src) \
    asm volatile("cp.async.cg.shared.global [%0], [%1], 16;" :: "r"(dst), "l"(src))
#define CP_COMMIT()  asm volatile("cp.async.commit_group;" ::: "memory")
#define CP_WAIT(n)   asm volatile("cp.async.wait_group %0;" :: "n"(n) : "memory")

// ---------------- precompute ----------------
extern "C" __global__ void convA_kernel(const float* __restrict__ im)
{
    size_t idx = (size_t)blockIdx.x * blockDim.x + threadIdx.x;
    if (idx >= (size_t)I_N * O_N * D_N) return;
    float a = im[idx];
    __nv_bfloat16 hi = __float2bfloat16(a);
    __nv_bfloat16 lo = __float2bfloat16(a - __bfloat162float(hi));
    gAh[idx] = hi; gAl[idx] = lo;
}

// Pad words [clen, 64) with a COPY of word clen-1: max over any computed
// superset of columns then equals the true max -> no masking in epilogue.
extern "C" __global__ void convB_kernel(const float* __restrict__ s,
                                        const int* __restrict__ s_l)
{
    size_t idx = (size_t)blockIdx.x * blockDim.x + threadIdx.x;
    if (idx >= (size_t)C_N * 64 * D_N) return;
    int d = idx & 63;
    int w = ((int)idx >> 6) & 63;
    int c = (int)(idx >> 12);
    int clen = s_l[c];
    int ws = (w < clen) ? w : (clen - 1);
    float v = s[((size_t)c * W_N + ws) * D_N + d];
    gBh[idx] = __float2bfloat16(v);
}

// ---------------- main xattn-scores kernel ----------------
extern "C" __global__ void __launch_bounds__(THREADS, 1)
xattn_kernel(const int* __restrict__ im_l, const int* __restrict__ s_l)
{
    extern __shared__ char smraw[];
    const uint32_t raw_u = smem_u32(smraw);
    const uint32_t abase = (raw_u + 1023u) & ~1023u;
    char* base = smraw + (abase - raw_u);

    const int tid  = threadIdx.x;
    const int wid  = tid >> 5;
    const int lane = tid & 31;
    const int img0 = blockIdx.x * IMG_PER_CTA;
    const int n_img = (I_N - img0 < IMG_PER_CTA) ? (I_N - img0) : IMG_PER_CTA;

    float* rmax = (float*)(base + OFF_RMAX);
    float* inv  = (float*)(base + OFF_INV);
    if (tid < n_img)
        inv[tid] = 1.0f / ((float)im_l[img0 + tid] + 1e-6f);

    // ---- stage A (hi/lo) into swizzled smem; zero-pad rows >= n_img*36 ----
    {
        const int vchunks = n_img * O_N * 8;
        const uint4* gh = (const uint4*)(gAh + (size_t)img0 * O_N * D_N);
        const uint4* gl = (const uint4*)(gAl + (size_t)img0 * O_N * D_N);
        const uint4 z = make_uint4(0, 0, 0, 0);
        #pragma unroll
        for (int t = tid; t < 2048; t += THREADS) {
            uint32_t off = SW128((uint32_t)(t * 16));
            *(uint4*)(base + OFF_AH + off) = (t < vchunks) ? gh[t] : z;
            *(uint4*)(base + OFF_AL + off) = (t < vchunks) ? gl[t] : z;
        }
    }

    // ---- prefetch B(0): 8 KB ----
    {
        const char* sh = (const char*)(gBh);
        uint32_t dst = abase + OFF_B;
        #pragma unroll
        for (int t = tid; t < 512; t += THREADS) {
            uint32_t off = SW128((uint32_t)(t * 16));
            CP16(dst + off, sh + t * 16);
        }
    }
    CP_COMMIT();
    __syncthreads();

    // ---- ldmatrix addressing invariants ----
    const uint32_t xr    = (uint32_t)((lane & 7) << 4);
    const uint32_t aColB = (uint32_t)((lane >> 4) << 4);
    const uint32_t bColB = (uint32_t)(((lane >> 3) & 1) << 4);
    const uint32_t aRow0 = (uint32_t)(wid * 16 + (lane & 15));
    const uint32_t aRow1 = aRow0 + 128;
    const uint32_t bRowOff = (uint32_t)((lane & 7) * 128);

    // ---- A fragments resident in registers for the whole caption loop ----
    uint32_t ah0[4][4], ah1[4][4], al0[4][4], al1[4][4];
    #pragma unroll
    for (int k = 0; k < 4; ++k) {
        const uint32_t colA = (aColB + (uint32_t)(k * 32)) ^ xr;
        ldsm4(ah0[k], abase + OFF_AH + aRow0 * 128 + colA);
        ldsm4(ah1[k], abase + OFF_AH + aRow1 * 128 + colA);
        ldsm4(al0[k], abase + OFF_AL + aRow0 * 128 + colA);
        ldsm4(al1[k], abase + OFF_AL + aRow1 * 128 + colA);
    }

    for (int c = 0; c < C_N; ++c) {
        // prefetch B(c+1)
        if (c + 1 < C_N) {
            const char* sh = (const char*)(gBh + (size_t)(c + 1) * 4096);
            uint32_t dst = abase + OFF_B + (uint32_t)((c + 1) & 1) * 8192;
            #pragma unroll
            for (int t = tid; t < 512; t += THREADS) {
                uint32_t off = SW128((uint32_t)(t * 16));
                CP16(dst + off, sh + t * 16);
            }
            CP_COMMIT();
            CP_WAIT(1);
        } else {
            CP_WAIT(0);
        }
        __syncthreads();   // B(c) ready; prev rmax reads done

        const int clen = __ldg(&s_l[c]);
        const int np = (clen + 15) >> 4;      // n-tile PAIRS to compute
        const uint32_t bh_base = abase + OFF_B + (uint32_t)(c & 1) * 8192;

        float mx[4] = { -1e30f, -1e30f, -1e30f, -1e30f };

        #pragma unroll
        for (int p = 0; p < 4; ++p) {
            if (p < np) {
                // load both tiles' B frags for all 4 k-steps (8 independent ldsm2)
                uint32_t bf[2][4][2];
                #pragma unroll
                for (int t2 = 0; t2 < 2; ++t2)
                    #pragma unroll
                    for (int k = 0; k < 4; ++k)
                        ldsm2(bf[t2][k], bh_base + (uint32_t)((2 * p + t2) * 1024)
                                        + bRowOff + ((bColB + (uint32_t)(k * 32)) ^ xr));

                float acc[2][2][4];
                #pragma unroll
                for (int m = 0; m < 2; ++m)
                    #pragma unroll
                    for (int t2 = 0; t2 < 2; ++t2)
                        #pragma unroll
                        for (int j = 0; j < 4; ++j) acc[m][t2][j] = 0.0f;

                #pragma unroll
                for (int k = 0; k < 4; ++k) {
                    #pragma unroll
                    for (int t2 = 0; t2 < 2; ++t2) {
                        mma16816(acc[0][t2], ah0[k], bf[t2][k]);
                        mma16816(acc[1][t2], ah1[k], bf[t2][k]);
                        mma16816(acc[0][t2], al0[k], bf[t2][k]);
                        mma16816(acc[1][t2], al1[k], bf[t2][k]);
                    }
                }

                // unconditional max (duplicate-padded B makes this exact)
                #pragma unroll
                for (int t2 = 0; t2 < 2; ++t2) {
                    mx[0] = fmaxf(mx[0], fmaxf(acc[0][t2][0], acc[0][t2][1]));
                    mx[1] = fmaxf(mx[1], fmaxf(acc[0][t2][2], acc[0][t2][3]));
                    mx[2] = fmaxf(mx[2], fmaxf(acc[1][t2][0], acc[1][t2][1]));
                    mx[3] = fmaxf(mx[3], fmaxf(acc[1][t2][2], acc[1][t2][3]));
                }
            }
        }

        // quad reduce (lanes sharing the same rows)
        #pragma unroll
        for (int j = 0; j < 4; ++j) {
            mx[j] = fmaxf(mx[j], __shfl_xor_sync(0xFFFFFFFFu, mx[j], 1));
            mx[j] = fmaxf(mx[j], __shfl_xor_sync(0xFFFFFFFFu, mx[j], 2));
        }
        if ((lane & 3) == 0) {
            const int row0 = wid * 16 + (lane >> 2);
            rmax[row0]       = mx[0];
            rmax[row0 + 8]   = mx[1];
            rmax[row0 + 128] = mx[2];
            rmax[row0 + 136] = mx[3];
        }
        __syncthreads();   // rmax ready

        if (tid < n_img) {
            float ssum = 0.0f;
            #pragma unroll
            for (int o = 0; o < O_N; ++o) ssum += rmax[tid * O_N + o];
            g_scores[(size_t)(img0 + tid) * C_N + c] = ssum * inv[tid];
        }
        // WAR on rmax covered by top-of-loop syncthreads
    }
}

// ---------------- loss epilogue ----------------
extern "C" __global__ void diag_kernel()
{
    int i = blockIdx.x * blockDim.x + threadIdx.x;
    if (i < I_N) g_diag[i] = g_scores[(size_t)i * C_N + i];
}

extern "C" __global__ void row_kernel()
{
    const int b = blockIdx.x;
    const int tid = threadIdx.x;
    const float di = g_diag[b];
    float local = 0.0f;
    for (int c = tid; c < C_N; c += blockDim.x) {
        if (c == b) continue;
        float sc = g_scores[(size_t)b * C_N + c];
        local += fmaxf(0.0f, MARGIN + sc - di)
               + fmaxf(0.0f, MARGIN + sc - g_diag[c]);
    }
    __shared__ float buf[128];
    buf[tid] = local;
    __syncthreads();
    for (int s = 64; s > 0; s >>= 1) {
        if (tid < s) buf[tid] += buf[tid + s];
        __syncthreads();
    }
    if (tid == 0) g_partial[b] = buf[0];
}

extern "C" __global__ void final_kernel(float* out)
{
    const int tid = threadIdx.x;
    float local = 0.0f;
    for (int i = tid; i < I_N; i += 256) local += g_partial[i];
    __shared__ float buf[256];
    buf[tid] = local;
    __syncthreads();
    for (int s = 128; s > 0; s >>= 1) {
        if (tid < s) buf[tid] += buf[tid + s];
        __syncthreads();
    }
    if (tid == 0) out[0] = buf[0] * (1.0f / ((float)I_N * (float)C_N));
}

// ---------------- launch ----------------
extern "C" void kernel_launch(void* const* d_in, const int* in_sizes, int n_in,
                              void* d_out, int out_size)
{
    const float* im   = (const float*)d_in[0];
    const float* s    = (const float*)d_in[1];
    const int*   im_l = (const int*)d_in[2];
    const int*   s_l  = (const int*)d_in[3];

    cudaFuncSetAttribute(xattn_kernel,
                         cudaFuncAttributeMaxDynamicSharedMemorySize, SMEM_BYTES);

    convA_kernel<<<(I_N * O_N * D_N + 255) / 256, 256>>>(im);
    convB_kernel<<<(C_N * 64 * D_N + 255) / 256, 256>>>(s, s_l);
    xattn_kernel<<<NCTA, THREADS, SMEM_BYTES>>>(im_l, s_l);
    diag_kernel<<<I_N / 256, 256>>>();
    row_kernel<<<I_N, 128>>>();
    final_kernel<<<1, 256>>>((float*)d_out);
}

// round 5
// speedup vs baseline: 5.9784x; 1.4545x over previous
#include <cuda_runtime.h>
#include <cuda_bf16.h>
#include <stdint.h>

// ---------------- problem constants ----------------
#define I_N 1024
#define O_N 36
#define C_N 1024
#define W_N 60
#define D_N 64
#define MARGIN 0.2f

#define IMG_PER_CTA 7
#define NCTA 147            // ceil(1024/7)
#define THREADS 256         // 8 warps; warp w owns m16-tiles w and w+8 (256 rows)

// ---------------- smem layout (bytes from 1024-aligned base) ----------------
#define OFF_A    0          // 256 rows x 128B (bf16)          = 32768
#define OFF_B    32768      // 2 bufs x 16KB (2 captions each) = 32768
#define OFF_RMAX 65536      // 2 x 256 floats                  = 2048
#define OFF_INV  67584      // 7 floats
#define SMEM_BYTES (67616 + 1024)

// ---------------- device globals ----------------
__device__ __nv_bfloat16 gA [(size_t)I_N * O_N * D_N];
__device__ __nv_bfloat16 gBh[(size_t)C_N * 64 * D_N];   // words padded to 64 w/ duplicate of last valid word
__device__ float g_scores[(size_t)I_N * C_N];
__device__ float g_diag[I_N];
__device__ float g_partial[I_N];

// ---------------- helpers ----------------
__device__ __forceinline__ uint32_t smem_u32(const void* p) {
    uint32_t a;
    asm("{ .reg .u64 t; cvta.to.shared.u64 t, %1; cvt.u32.u64 %0, t; }" : "=r"(a) : "l"(p));
    return a;
}
#define SW128(off) ((off) ^ (((off) >> 3) & 0x70))

__device__ __forceinline__ void ldsm4(uint32_t* r, uint32_t addr) {
    asm volatile("ldmatrix.sync.aligned.m8n8.x4.shared.b16 {%0,%1,%2,%3}, [%4];"
                 : "=r"(r[0]), "=r"(r[1]), "=r"(r[2]), "=r"(r[3]) : "r"(addr));
}
__device__ __forceinline__ void ldsm2(uint32_t* r, uint32_t addr) {
    asm volatile("ldmatrix.sync.aligned.m8n8.x2.shared.b16 {%0,%1}, [%2];"
                 : "=r"(r[0]), "=r"(r[1]) : "r"(addr));
}
__device__ __forceinline__ void mma16816(float* d, const uint32_t* a, const uint32_t* b) {
    asm volatile(
        "mma.sync.aligned.m16n8k16.row.col.f32.bf16.bf16.f32 "
        "{%0,%1,%2,%3}, {%4,%5,%6,%7}, {%8,%9}, {%0,%1,%2,%3};"
        : "+f"(d[0]), "+f"(d[1]), "+f"(d[2]), "+f"(d[3])
        : "r"(a[0]), "r"(a[1]), "r"(a[2]), "r"(a[3]), "r"(b[0]), "r"(b[1]));
}
#define CP16(dst, src) \
    asm volatile("cp.async.cg.shared.global [%0], [%1], 16;" :: "r"(dst), "l"(src))
#define CP_COMMIT()  asm volatile("cp.async.commit_group;" ::: "memory")
#define CP_WAIT(n)   asm volatile("cp.async.wait_group %0;" :: "n"(n) : "memory")

// ---------------- precompute ----------------
extern "C" __global__ void convA_kernel(const float* __restrict__ im)
{
    size_t idx = (size_t)blockIdx.x * blockDim.x + threadIdx.x;
    if (idx >= (size_t)I_N * O_N * D_N) return;
    gA[idx] = __float2bfloat16(im[idx]);
}

// Pad words [clen, 64) with a COPY of word clen-1: max over any computed
// superset of columns equals the true max -> no masking needed downstream.
extern "C" __global__ void convB_kernel(const float* __restrict__ s,
                                        const int* __restrict__ s_l)
{
    size_t idx = (size_t)blockIdx.x * blockDim.x + threadIdx.x;
    if (idx >= (size_t)C_N * 64 * D_N) return;
    int d = idx & 63;
    int w = ((int)idx >> 6) & 63;
    int c = (int)(idx >> 12);
    int clen = s_l[c];
    int ws = (w < clen) ? w : (clen - 1);
    gBh[idx] = __float2bfloat16(s[((size_t)c * W_N + ws) * D_N + d]);
}

// ---------------- main xattn-scores kernel ----------------
extern "C" __global__ void __launch_bounds__(THREADS, 1)
xattn_kernel(const int* __restrict__ im_l, const int* __restrict__ s_l)
{
    extern __shared__ char smraw[];
    const uint32_t raw_u = smem_u32(smraw);
    const uint32_t abase = (raw_u + 1023u) & ~1023u;
    char* base = smraw + (abase - raw_u);

    const int tid  = threadIdx.x;
    const int wid  = tid >> 5;
    const int lane = tid & 31;
    const int img0 = blockIdx.x * IMG_PER_CTA;
    const int n_img = (I_N - img0 < IMG_PER_CTA) ? (I_N - img0) : IMG_PER_CTA;

    float* rmax = (float*)(base + OFF_RMAX);   // [2][256]
    float* inv  = (float*)(base + OFF_INV);
    if (tid < n_img)
        inv[tid] = 1.0f / ((float)im_l[img0 + tid] + 1e-6f);

    // ---- stage A into swizzled smem; zero-pad rows >= n_img*36 ----
    {
        const int vchunks = n_img * O_N * 8;
        const uint4* ga = (const uint4*)(gA + (size_t)img0 * O_N * D_N);
        const uint4 z = make_uint4(0, 0, 0, 0);
        #pragma unroll
        for (int t = tid; t < 2048; t += THREADS) {
            uint32_t off = SW128((uint32_t)(t * 16));
            *(uint4*)(base + OFF_A + off) = (t < vchunks) ? ga[t] : z;
        }
    }

    // ---- prefetch B pair 0 (captions 0,1): 16 KB ----
    {
        const char* sh = (const char*)(gBh);
        uint32_t dst = abase + OFF_B;
        #pragma unroll
        for (int t = tid; t < 1024; t += THREADS) {
            uint32_t off = SW128((uint32_t)(t * 16));
            CP16(dst + off, sh + t * 16);
        }
    }
    CP_COMMIT();
    __syncthreads();

    // ---- ldmatrix addressing invariants ----
    const uint32_t xr    = (uint32_t)((lane & 7) << 4);
    const uint32_t aColB = (uint32_t)((lane >> 4) << 4);
    const uint32_t bColB = (uint32_t)(((lane >> 3) & 1) << 4);
    const uint32_t aRow0 = (uint32_t)(wid * 16 + (lane & 15));
    const uint32_t aRow1 = aRow0 + 128;
    const uint32_t bRowOff = (uint32_t)((lane & 7) * 128);

    // ---- A fragments resident in registers for the whole caption loop ----
    uint32_t ah0[4][4], ah1[4][4];
    #pragma unroll
    for (int k = 0; k < 4; ++k) {
        const uint32_t colA = (aColB + (uint32_t)(k * 32)) ^ xr;
        ldsm4(ah0[k], abase + OFF_A + aRow0 * 128 + colA);
        ldsm4(ah1[k], abase + OFF_A + aRow1 * 128 + colA);
    }

    const int NPAIR = C_N / 2;
    for (int cc = 0; cc < NPAIR; ++cc) {
        // prefetch next caption pair (16 KB)
        if (cc + 1 < NPAIR) {
            const char* sh = (const char*)(gBh + (size_t)(cc + 1) * 8192);
            uint32_t dst = abase + OFF_B + (uint32_t)((cc + 1) & 1) * 16384;
            #pragma unroll
            for (int t = tid; t < 1024; t += THREADS) {
                uint32_t off = SW128((uint32_t)(t * 16));
                CP16(dst + off, sh + t * 16);
            }
            CP_COMMIT();
            CP_WAIT(1);
        } else {
            CP_WAIT(0);
        }
        __syncthreads();   // pair (cc) B ready; prev-pair rmax reads complete

        #pragma unroll
        for (int j = 0; j < 2; ++j) {
            const int c = 2 * cc + j;
            const int clen = __ldg(&s_l[c]);
            const int np = (clen + 15) >> 4;   // n-tile pairs to compute
            const uint32_t bh_base = abase + OFF_B + (uint32_t)(cc & 1) * 16384
                                    + (uint32_t)j * 8192;

            float mx[4] = { -1e30f, -1e30f, -1e30f, -1e30f };

            #pragma unroll
            for (int p = 0; p < 4; ++p) {
                if (p < np) {
                    uint32_t bf[2][4][2];
                    #pragma unroll
                    for (int t2 = 0; t2 < 2; ++t2)
                        #pragma unroll
                        for (int k = 0; k < 4; ++k)
                            ldsm2(bf[t2][k], bh_base + (uint32_t)((2 * p + t2) * 1024)
                                            + bRowOff + ((bColB + (uint32_t)(k * 32)) ^ xr));

                    float acc[2][2][4];
                    #pragma unroll
                    for (int m = 0; m < 2; ++m)
                        #pragma unroll
                        for (int t2 = 0; t2 < 2; ++t2)
                            #pragma unroll
                            for (int q = 0; q < 4; ++q) acc[m][t2][q] = 0.0f;

                    #pragma unroll
                    for (int k = 0; k < 4; ++k) {
                        #pragma unroll
                        for (int t2 = 0; t2 < 2; ++t2) {
                            mma16816(acc[0][t2], ah0[k], bf[t2][k]);
                            mma16816(acc[1][t2], ah1[k], bf[t2][k]);
                        }
                    }

                    #pragma unroll
                    for (int t2 = 0; t2 < 2; ++t2) {
                        mx[0] = fmaxf(mx[0], fmaxf(acc[0][t2][0], acc[0][t2][1]));
                        mx[1] = fmaxf(mx[1], fmaxf(acc[0][t2][2], acc[0][t2][3]));
                        mx[2] = fmaxf(mx[2], fmaxf(acc[1][t2][0], acc[1][t2][1]));
                        mx[3] = fmaxf(mx[3], fmaxf(acc[1][t2][2], acc[1][t2][3]));
                    }
                }
            }

            // quad reduce (lanes sharing the same rows)
            #pragma unroll
            for (int q = 0; q < 4; ++q) {
                mx[q] = fmaxf(mx[q], __shfl_xor_sync(0xFFFFFFFFu, mx[q], 1));
                mx[q] = fmaxf(mx[q], __shfl_xor_sync(0xFFFFFFFFu, mx[q], 2));
            }
            if ((lane & 3) == 0) {
                float* rj = rmax + j * 256;
                const int row0 = wid * 16 + (lane >> 2);
                rj[row0]       = mx[0];
                rj[row0 + 8]   = mx[1];
                rj[row0 + 128] = mx[2];
                rj[row0 + 136] = mx[3];
            }
        }
        __syncthreads();   // both captions' rmax ready

        if (tid < n_img) {
            const float iv = inv[tid];
            float s0 = 0.0f, s1 = 0.0f;
            #pragma unroll
            for (int o = 0; o < O_N; ++o) {
                s0 += rmax[tid * O_N + o];
                s1 += rmax[256 + tid * O_N + o];
            }
            float* dst = &g_scores[(size_t)(img0 + tid) * C_N + 2 * cc];
            dst[0] = s0 * iv;
            dst[1] = s1 * iv;
        }
        // WAR on rmax covered by next pair's B-ready syncthreads
    }
}

// ---------------- loss epilogue ----------------
extern "C" __global__ void diag_kernel()
{
    int i = blockIdx.x * blockDim.x + threadIdx.x;
    if (i < I_N) g_diag[i] = g_scores[(size_t)i * C_N + i];
}

extern "C" __global__ void row_kernel()
{
    const int b = blockIdx.x;
    const int tid = threadIdx.x;
    const float di = g_diag[b];
    float local = 0.0f;
    for (int c = tid; c < C_N; c += blockDim.x) {
        if (c == b) continue;
        float sc = g_scores[(size_t)b * C_N + c];
        local += fmaxf(0.0f, MARGIN + sc - di)
               + fmaxf(0.0f, MARGIN + sc - g_diag[c]);
    }
    __shared__ float buf[128];
    buf[tid] = local;
    __syncthreads();
    for (int s = 64; s > 0; s >>= 1) {
        if (tid < s) buf[tid] += buf[tid + s];
        __syncthreads();
    }
    if (tid == 0) g_partial[b] = buf[0];
}

extern "C" __global__ void final_kernel(float* out)
{
    const int tid = threadIdx.x;
    float local = 0.0f;
    for (int i = tid; i < I_N; i += 256) local += g_partial[i];
    __shared__ float buf[256];
    buf[tid] = local;
    __syncthreads();
    for (int s = 128; s > 0; s >>= 1) {
        if (tid < s) buf[tid] += buf[tid + s];
        __syncthreads();
    }
    if (tid == 0) out[0] = buf[0] * (1.0f / ((float)I_N * (float)C_N));
}

// ---------------- launch ----------------
extern "C" void kernel_launch(void* const* d_in, const int* in_sizes, int n_in,
                              void* d_out, int out_size)
{
    const float* im   = (const float*)d_in[0];
    const float* s    = (const float*)d_in[1];
    const int*   im_l = (const int*)d_in[2];
    const int*   s_l  = (const int*)d_in[3];

    cudaFuncSetAttribute(xattn_kernel,
                         cudaFuncAttributeMaxDynamicSharedMemorySize, SMEM_BYTES);

    convA_kernel<<<(I_N * O_N * D_N + 255) / 256, 256>>>(im);
    convB_kernel<<<(C_N * 64 * D_N + 255) / 256, 256>>>(s, s_l);
    xattn_kernel<<<NCTA, THREADS, SMEM_BYTES>>>(im_l, s_l);
    diag_kernel<<<I_N / 256, 256>>>();
    row_kernel<<<I_N, 128>>>();
    final_kernel<<<1, 256>>>((float*)d_out);
}

// round 6
// speedup vs baseline: 7.1277x; 1.1922x over previous
#include <cuda_runtime.h>
#include <cuda_bf16.h>
#include <stdint.h>

// ---------------- problem constants ----------------
#define I_N 1024
#define O_N 36
#define C_N 1024
#define W_N 60
#define D_N 64
#define MARGIN 0.2f

#define IMG_PER_CTA 7
#define NCTA 147            // ceil(1024/7)
#define THREADS 256         // 8 warps; warp w owns m16-tiles w and w+8 (256 rows)
#define CAP_BATCH 4         // captions per B buffer
#define NBATCH (C_N / CAP_BATCH)

// ---------------- smem layout (bytes from 1024-aligned base) ----------------
#define OFF_A    0          // 256 rows x 128B (bf16)            = 32768
#define OFF_B    32768      // 2 bufs x 32KB (4 captions each)   = 65536
#define OFF_RMAX 98304      // 4 x 256 floats                    = 4096
#define OFF_INV  102400     // 7 floats
#define SMEM_BYTES (102432 + 1024)

// ---------------- device globals ----------------
__device__ __nv_bfloat16 gA [(size_t)I_N * O_N * D_N];
__device__ __nv_bfloat16 gBh[(size_t)C_N * 64 * D_N];   // words padded to 64 w/ duplicate of last valid word
__device__ float g_scores[(size_t)I_N * C_N];
__device__ float g_diag[I_N];
__device__ float g_partial[I_N];

// ---------------- helpers ----------------
__device__ __forceinline__ uint32_t smem_u32(const void* p) {
    uint32_t a;
    asm("{ .reg .u64 t; cvta.to.shared.u64 t, %1; cvt.u32.u64 %0, t; }" : "=r"(a) : "l"(p));
    return a;
}
#define SW128(off) ((off) ^ (((off) >> 3) & 0x70))

__device__ __forceinline__ void ldsm4(uint32_t* r, uint32_t addr) {
    asm volatile("ldmatrix.sync.aligned.m8n8.x4.shared.b16 {%0,%1,%2,%3}, [%4];"
                 : "=r"(r[0]), "=r"(r[1]), "=r"(r[2]), "=r"(r[3]) : "r"(addr));
}
__device__ __forceinline__ void mma16816(float* d, const uint32_t* a, const uint32_t* b) {
    asm volatile(
        "mma.sync.aligned.m16n8k16.row.col.f32.bf16.bf16.f32 "
        "{%0,%1,%2,%3}, {%4,%5,%6,%7}, {%8,%9}, {%0,%1,%2,%3};"
        : "+f"(d[0]), "+f"(d[1]), "+f"(d[2]), "+f"(d[3])
        : "r"(a[0]), "r"(a[1]), "r"(a[2]), "r"(a[3]), "r"(b[0]), "r"(b[1]));
}
#define CP16(dst, src) \
    asm volatile("cp.async.cg.shared.global [%0], [%1], 16;" :: "r"(dst), "l"(src))
#define CP_COMMIT()  asm volatile("cp.async.commit_group;" ::: "memory")
#define CP_WAIT(n)   asm volatile("cp.async.wait_group %0;" :: "n"(n) : "memory")

// ---------------- precompute ----------------
extern "C" __global__ void convA_kernel(const float* __restrict__ im)
{
    size_t idx = (size_t)blockIdx.x * blockDim.x + threadIdx.x;
    if (idx >= (size_t)I_N * O_N * D_N) return;
    gA[idx] = __float2bfloat16(im[idx]);
}

// Pad words [clen, 64) with a COPY of word clen-1: max over any computed
// superset of columns equals the true max -> no masking needed downstream.
extern "C" __global__ void convB_kernel(const float* __restrict__ s,
                                        const int* __restrict__ s_l)
{
    size_t idx = (size_t)blockIdx.x * blockDim.x + threadIdx.x;
    if (idx >= (size_t)C_N * 64 * D_N) return;
    int d = idx & 63;
    int w = ((int)idx >> 6) & 63;
    int c = (int)(idx >> 12);
    int clen = s_l[c];
    int ws = (w < clen) ? w : (clen - 1);
    gBh[idx] = __float2bfloat16(s[((size_t)c * W_N + ws) * D_N + d]);
}

// ---------------- main xattn-scores kernel ----------------
extern "C" __global__ void __launch_bounds__(THREADS, 1)
xattn_kernel(const int* __restrict__ im_l, const int* __restrict__ s_l)
{
    extern __shared__ char smraw[];
    const uint32_t raw_u = smem_u32(smraw);
    const uint32_t abase = (raw_u + 1023u) & ~1023u;
    char* base = smraw + (abase - raw_u);

    const int tid  = threadIdx.x;
    const int wid  = tid >> 5;
    const int lane = tid & 31;
    const int img0 = blockIdx.x * IMG_PER_CTA;
    const int n_img = (I_N - img0 < IMG_PER_CTA) ? (I_N - img0) : IMG_PER_CTA;

    float* rmax = (float*)(base + OFF_RMAX);   // [4][256]
    float* inv  = (float*)(base + OFF_INV);
    if (tid < n_img)
        inv[tid] = 1.0f / ((float)im_l[img0 + tid] + 1e-6f);

    // ---- stage A into swizzled smem; zero-pad rows >= n_img*36 ----
    {
        const int vchunks = n_img * O_N * 8;
        const uint4* ga = (const uint4*)(gA + (size_t)img0 * O_N * D_N);
        const uint4 z = make_uint4(0, 0, 0, 0);
        #pragma unroll
        for (int t = tid; t < 2048; t += THREADS) {
            uint32_t off = SW128((uint32_t)(t * 16));
            *(uint4*)(base + OFF_A + off) = (t < vchunks) ? ga[t] : z;
        }
    }

    // ---- prefetch B batch 0 (captions 0..3): 32 KB ----
    {
        const char* sh = (const char*)(gBh);
        uint32_t dst = abase + OFF_B;
        #pragma unroll
        for (int t = tid; t < 2048; t += THREADS) {
            uint32_t off = SW128((uint32_t)(t * 16));
            CP16(dst + off, sh + t * 16);
        }
    }
    CP_COMMIT();
    __syncthreads();

    // ---- ldmatrix addressing invariants ----
    const uint32_t xr    = (uint32_t)((lane & 7) << 4);
    const uint32_t aColB = (uint32_t)((lane >> 4) << 4);
    const uint32_t aRow0 = (uint32_t)(wid * 16 + (lane & 15));
    const uint32_t aRow1 = aRow0 + 128;
    // B ldsm4: lane L -> row (L&7), matrix (L>>3); matrices = 4 consecutive
    // 16B k-chunks => one x4 load covers 2 k-steps of one n-tile.
    const uint32_t bRowOff = (uint32_t)((lane & 7) * 128);
    const uint32_t bMat    = (uint32_t)((lane >> 3) << 4);

    // ---- A fragments resident in registers for the whole caption loop ----
    uint32_t ah0[4][4], ah1[4][4];
    #pragma unroll
    for (int k = 0; k < 4; ++k) {
        const uint32_t colA = (aColB + (uint32_t)(k * 32)) ^ xr;
        ldsm4(ah0[k], abase + OFF_A + aRow0 * 128 + colA);
        ldsm4(ah1[k], abase + OFF_A + aRow1 * 128 + colA);
    }

    for (int cc = 0; cc < NBATCH; ++cc) {
        // prefetch next batch (32 KB)
        if (cc + 1 < NBATCH) {
            const char* sh = (const char*)(gBh + (size_t)(cc + 1) * 16384);
            uint32_t dst = abase + OFF_B + (uint32_t)((cc + 1) & 1) * 32768;
            #pragma unroll
            for (int t = tid; t < 2048; t += THREADS) {
                uint32_t off = SW128((uint32_t)(t * 16));
                CP16(dst + off, sh + t * 16);
            }
            CP_COMMIT();
            CP_WAIT(1);
        } else {
            CP_WAIT(0);
        }
        __syncthreads();   // batch (cc) B ready; prev-batch rmax reads complete

        #pragma unroll
        for (int j = 0; j < CAP_BATCH; ++j) {
            const int c = CAP_BATCH * cc + j;
            const int clen = __ldg(&s_l[c]);
            const int nlim = (clen + 7) >> 3;      // n8 tiles to compute
            const uint32_t bh_base = abase + OFF_B + (uint32_t)((cc & 1) << 15)
                                    + (uint32_t)(j << 13);

            float mx[4] = { -1e30f, -1e30f, -1e30f, -1e30f };

            #pragma unroll
            for (int p = 0; p < 4; ++p) {
                const int n0 = 2 * p;
                if (n0 < nlim) {
                    const bool has2 = (n0 + 1) < nlim;
                    // bf[t2][kp][0..3]: {r0,r1}=k-step 2kp, {r2,r3}=k-step 2kp+1
                    uint32_t bf0[2][4], bf1[2][4];
                    #pragma unroll
                    for (int kp = 0; kp < 2; ++kp)
                        ldsm4(bf0[kp], bh_base + (uint32_t)(n0 * 1024) + bRowOff
                                      + (((uint32_t)(kp * 64) + bMat) ^ xr));
                    if (has2) {
                        #pragma unroll
                        for (int kp = 0; kp < 2; ++kp)
                            ldsm4(bf1[kp], bh_base + (uint32_t)((n0 + 1) * 1024) + bRowOff
                                          + (((uint32_t)(kp * 64) + bMat) ^ xr));
                    }

                    float acc[2][2][4];
                    #pragma unroll
                    for (int m = 0; m < 2; ++m)
                        #pragma unroll
                        for (int t2 = 0; t2 < 2; ++t2)
                            #pragma unroll
                            for (int q = 0; q < 4; ++q) acc[m][t2][q] = 0.0f;

                    #pragma unroll
                    for (int k = 0; k < 4; ++k) {
                        const uint32_t* b0 = &bf0[k >> 1][(k & 1) * 2];
                        mma16816(acc[0][0], ah0[k], b0);
                        mma16816(acc[1][0], ah1[k], b0);
                        if (has2) {
                            const uint32_t* b1 = &bf1[k >> 1][(k & 1) * 2];
                            mma16816(acc[0][1], ah0[k], b1);
                            mma16816(acc[1][1], ah1[k], b1);
                        }
                    }

                    mx[0] = fmaxf(mx[0], fmaxf(acc[0][0][0], acc[0][0][1]));
                    mx[1] = fmaxf(mx[1], fmaxf(acc[0][0][2], acc[0][0][3]));
                    mx[2] = fmaxf(mx[2], fmaxf(acc[1][0][0], acc[1][0][1]));
                    mx[3] = fmaxf(mx[3], fmaxf(acc[1][0][2], acc[1][0][3]));
                    if (has2) {
                        mx[0] = fmaxf(mx[0], fmaxf(acc[0][1][0], acc[0][1][1]));
                        mx[1] = fmaxf(mx[1], fmaxf(acc[0][1][2], acc[0][1][3]));
                        mx[2] = fmaxf(mx[2], fmaxf(acc[1][1][0], acc[1][1][1]));
                        mx[3] = fmaxf(mx[3], fmaxf(acc[1][1][2], acc[1][1][3]));
                    }
                }
            }

            // quad reduce (lanes sharing the same rows)
            #pragma unroll
            for (int q = 0; q < 4; ++q) {
                mx[q] = fmaxf(mx[q], __shfl_xor_sync(0xFFFFFFFFu, mx[q], 1));
                mx[q] = fmaxf(mx[q], __shfl_xor_sync(0xFFFFFFFFu, mx[q], 2));
            }
            if ((lane & 3) == 0) {
                float* rj = rmax + j * 256;
                const int row0 = wid * 16 + (lane >> 2);
                rj[row0]       = mx[0];
                rj[row0 + 8]   = mx[1];
                rj[row0 + 128] = mx[2];
                rj[row0 + 136] = mx[3];
            }
        }
        __syncthreads();   // all 4 captions' rmax ready

        // ---- warp-parallel score epilogue: warp w reduces image w ----
        if (wid < n_img) {
            const float iv = inv[wid];
            const int rbase = wid * O_N;
            #pragma unroll
            for (int j = 0; j < CAP_BATCH; ++j) {
                float v = rmax[j * 256 + rbase + lane];
                if (lane < O_N - 32) v += rmax[j * 256 + rbase + 32 + lane];
                #pragma unroll
                for (int o = 16; o > 0; o >>= 1)
                    v += __shfl_xor_sync(0xFFFFFFFFu, v, o);
                if (lane == 0)
                    g_scores[(size_t)(img0 + wid) * C_N + CAP_BATCH * cc + j] = v * iv;
            }
        }
        // WAR on rmax covered by next batch's B-ready syncthreads
    }
}

// ---------------- loss epilogue ----------------
extern "C" __global__ void diag_kernel()
{
    int i = blockIdx.x * blockDim.x + threadIdx.x;
    if (i < I_N) g_diag[i] = g_scores[(size_t)i * C_N + i];
}

extern "C" __global__ void row_kernel()
{
    const int b = blockIdx.x;
    const int tid = threadIdx.x;
    const float di = g_diag[b];
    float local = 0.0f;
    for (int c = tid; c < C_N; c += blockDim.x) {
        if (c == b) continue;
        float sc = g_scores[(size_t)b * C_N + c];
        local += fmaxf(0.0f, MARGIN + sc - di)
               + fmaxf(0.0f, MARGIN + sc - g_diag[c]);
    }
    __shared__ float buf[128];
    buf[tid] = local;
    __syncthreads();
    for (int s = 64; s > 0; s >>= 1) {
        if (tid < s) buf[tid] += buf[tid + s];
        __syncthreads();
    }
    if (tid == 0) g_partial[b] = buf[0];
}

extern "C" __global__ void final_kernel(float* out)
{
    const int tid = threadIdx.x;
    float local = 0.0f;
    for (int i = tid; i < I_N; i += 256) local += g_partial[i];
    __shared__ float buf[256];
    buf[tid] = local;
    __syncthreads();
    for (int s = 128; s > 0; s >>= 1) {
        if (tid < s) buf[tid] += buf[tid + s];
        __syncthreads();
    }
    if (tid == 0) out[0] = buf[0] * (1.0f / ((float)I_N * (float)C_N));
}

// ---------------- launch ----------------
extern "C" void kernel_launch(void* const* d_in, const int* in_sizes, int n_in,
                              void* d_out, int out_size)
{
    const float* im   = (const float*)d_in[0];
    const float* s    = (const float*)d_in[1];
    const int*   im_l = (const int*)d_in[2];
    const int*   s_l  = (const int*)d_in[3];

    cudaFuncSetAttribute(xattn_kernel,
                         cudaFuncAttributeMaxDynamicSharedMemorySize, SMEM_BYTES);

    convA_kernel<<<(I_N * O_N * D_N + 255) / 256, 256>>>(im);
    convB_kernel<<<(C_N * 64 * D_N + 255) / 256, 256>>>(s, s_l);
    xattn_kernel<<<NCTA, THREADS, SMEM_BYTES>>>(im_l, s_l);
    diag_kernel<<<I_N / 256, 256>>>();
    row_kernel<<<I_N, 128>>>();
    final_kernel<<<1, 256>>>((float*)d_out);
}